// round 16
// baseline (speedup 1.0000x reference)
#include <cuda_runtime.h>
#include <cuda_fp16.h>
#include <cstdint>

// AttenConv round 15: per-quarter pipelines + log2-domain flash epilogue.
// out[u,:] = softmax_i(adj?<U_u,V_i>:0) @ V @ W
// GEMM1: fp16 hi/lo 3-term on U' = U*log2(e)  => s' = s*log2e from the MMA.
// GEMM2: single fp16 term, p' = exp2(s' - m') <= 1.
// Round 15 vs 14:
//  (1) scores in log2 domain: every __expf becomes bare ex2.approx (no FMUL).
//  (2) p_raw = exp2(s'-m_old) issued BEFORE the shfl-max tree (overlap MUFU
//      with SHFL); den = (den + sum(p_raw))*sc; p' = p_raw*sc at pack.

#define U_DIM   8192
#define I_DIM   16384
#define D_DIM   64
#define OUT_DIM 64
#define BM      32          // users per CTA
#define BN      128         // items per tile
#define NCH     4           // item chunks (CTAs per u-block)
#define NTC     32          // tiles per CTA
#define VSTR    144         // bytes per 64-half row
#define QPLANE  4608        // one quarter plane: 32 rows * 144B
#define QBUF    9216        // hi+lo planes of one quarter buf
#define QSTRIDE 27648       // 3 bufs per quarter
#define LOG2E   1.44269504088896f

// smem layout: [quarter q][buf 0..2][hi|lo] then den/ms
#define SM_DEN  110592               // dens[4][32] 512 + ms[4][32] 512
#define SM_UH   9216                 // U hi [32][72] = quarter0 buf1 hi
#define SM_UL   13824                // U lo [32][72] = quarter0 buf1 lo
#define SM_NUMA 0                    // end-phase alias: num [4][32][68] fp32
#define SMEM_TOTAL 111616

__device__ __align__(16) __half g_vhi[I_DIM][72];
__device__ __align__(16) __half g_vlo[I_DIM][72];
__device__ __align__(16) float  g_pnum[1024][BM][D_DIM];
__device__ float g_pden[1024][BM];
__device__ float g_pm[1024][BM];      // log2-domain maxes

__device__ __forceinline__ uint32_t smem_u32(const void* p) {
    uint32_t a;
    asm("{ .reg .u64 t; cvta.to.shared.u64 t, %1; cvt.u32.u64 %0, t; }" : "=r"(a) : "l"(p));
    return a;
}
__device__ __forceinline__ void cp16(uint32_t dst, const void* src) {
    asm volatile("cp.async.cg.shared.global [%0], [%1], 16;" :: "r"(dst), "l"(src));
}
#define CP_COMMIT() asm volatile("cp.async.commit_group;" ::: "memory")
#define CP_WAIT1()  asm volatile("cp.async.wait_group 1;" ::: "memory")
#define PAIR_BAR(id) asm volatile("bar.sync %0, 64;" :: "r"(id) : "memory")

__device__ __forceinline__ float ex2(float x) {
    float y;
    asm("ex2.approx.f32 %0, %1;" : "=f"(y) : "f"(x));
    return y;
}

// NON-volatile: pure register op, lets ptxas schedule MMAs freely.
__device__ __forceinline__ void mma16816(float* d,
                                         const uint32_t* a,
                                         uint32_t b0, uint32_t b1) {
    asm("mma.sync.aligned.m16n8k16.row.col.f32.f16.f16.f32 "
        "{%0,%1,%2,%3},{%4,%5,%6,%7},{%8,%9},{%0,%1,%2,%3};"
        : "+f"(d[0]), "+f"(d[1]), "+f"(d[2]), "+f"(d[3])
        : "r"(a[0]), "r"(a[1]), "r"(a[2]), "r"(a[3]), "r"(b0), "r"(b1));
}
__device__ __forceinline__ void mma16816v(float* d,
                                          uint32_t a0, uint32_t a1, uint32_t a2, uint32_t a3,
                                          uint32_t b0, uint32_t b1) {
    asm("mma.sync.aligned.m16n8k16.row.col.f32.f16.f16.f32 "
        "{%0,%1,%2,%3},{%4,%5,%6,%7},{%8,%9},{%0,%1,%2,%3};"
        : "+f"(d[0]), "+f"(d[1]), "+f"(d[2]), "+f"(d[3])
        : "r"(a0), "r"(a1), "r"(a2), "r"(a3), "r"(b0), "r"(b1));
}
__device__ __forceinline__ void ldsm4(uint32_t* r, uint32_t addr) {
    asm volatile("ldmatrix.sync.aligned.m8n8.x4.shared.b16 {%0,%1,%2,%3}, [%4];"
                 : "=r"(r[0]), "=r"(r[1]), "=r"(r[2]), "=r"(r[3]) : "r"(addr));
}
__device__ __forceinline__ void ldsm4t(uint32_t& r0, uint32_t& r1, uint32_t& r2, uint32_t& r3,
                                       uint32_t addr) {
    asm volatile("ldmatrix.sync.aligned.m8n8.x4.trans.shared.b16 {%0,%1,%2,%3}, [%4];"
                 : "=r"(r0), "=r"(r1), "=r"(r2), "=r"(r3) : "r"(addr));
}
__device__ __forceinline__ uint32_t packh2(float x0, float x1) {
    uint32_t r;
    asm("cvt.rn.f16x2.f32 %0, %1, %2;" : "=r"(r) : "f"(x1), "f"(x0));
    return r;
}
__device__ __forceinline__ void split2h(float x0, float x1, uint32_t& h, uint32_t& l) {
    h = packh2(x0, x1);
    __half2 hv = *(__half2*)&h;
    float2 back = __half22float2(hv);
    l = packh2(x0 - back.x, x1 - back.y);
}

// ---- precompute: split item_emb into fp16 hi/lo planes with VSTR padding ----
__global__ void __launch_bounds__(256)
vsplit_kernel(const float* __restrict__ item_emb)
{
    const int gid  = blockIdx.x * 256 + threadIdx.x;
    const int item = gid >> 3;
    const int d0   = (gid & 7) * 8;
    const float4* vp = (const float4*)(item_emb + (long)item * D_DIM + d0);
    const float4 v0 = vp[0], v1 = vp[1];
    uint32_t h0, l0, h1, l1, h2, l2, h3, l3;
    split2h(v0.x, v0.y, h0, l0); split2h(v0.z, v0.w, h1, l1);
    split2h(v1.x, v1.y, h2, l2); split2h(v1.z, v1.w, h3, l3);
    *(uint4*)&g_vhi[item][d0] = make_uint4(h0, h1, h2, h3);
    *(uint4*)&g_vlo[item][d0] = make_uint4(l0, l1, l2, l3);
}

__global__ void __launch_bounds__(256, 2)
atten_hmma_kernel(const float* __restrict__ user_emb,
                  const int*   __restrict__ adj)
{
    extern __shared__ __align__(128) char smc[];
    const uint32_t sb = smem_u32(smc);
    const int tid = threadIdx.x;
    const int bid = blockIdx.x;
    const int ub  = bid >> 2;       // u-block
    const int ch  = bid & 3;        // item chunk
    const int w   = tid >> 5;
    const int l   = tid & 31;
    const int m   = w & 1;          // user group: rows 16m..16m+15
    const int q   = w >> 1;         // item quarter within tile
    const int u0  = ub * BM;
    const int tg0 = ch * NTC;       // first global tile index

    const char* vhib = (const char*)g_vhi;
    const char* vlob = (const char*)g_vlo;

    const uint32_t qbase = (uint32_t)q * QSTRIDE;        // smem quarter base
    const uint32_t half  = (uint32_t)m * 2304;

    // ---- prologue: stage U' = U*log2e hi/lo (quarter0 buf1); cp tile 0 ----
    {
        const int row = tid >> 3, d0 = (tid & 7) * 8;
        const float4* up = (const float4*)(user_emb + (long)(u0 + row) * D_DIM + d0);
        float4 v0 = up[0], v1 = up[1];
        v0.x *= LOG2E; v0.y *= LOG2E; v0.z *= LOG2E; v0.w *= LOG2E;
        v1.x *= LOG2E; v1.y *= LOG2E; v1.z *= LOG2E; v1.w *= LOG2E;
        uint32_t h0, l0h, h1, l1h, h2, l2h, h3, l3h;
        split2h(v0.x, v0.y, h0, l0h); split2h(v0.z, v0.w, h1, l1h);
        split2h(v1.x, v1.y, h2, l2h); split2h(v1.z, v1.w, h3, l3h);
        *(uint4*)(smc + SM_UH + row * VSTR + d0 * 2) = make_uint4(h0, h1, h2, h3);
        *(uint4*)(smc + SM_UL + row * VSTR + d0 * 2) = make_uint4(l0h, l1h, l2h, l3h);
    }
    {
        const long src = ((long)tg0 * 128 + 32 * q) * VSTR + half;
        const uint32_t dh = sb + qbase + half;       // buf 0 hi, own half
        const uint32_t dl = dh + QPLANE;             // buf 0 lo, own half
        #pragma unroll
        for (int k = 0; k < 5; k++) {
            const int idx = l + 32 * k;
            if (idx < 144) {
                cp16(dh + idx * 16, vhib + src + idx * 16);
                cp16(dl + idx * 16, vlob + src + idx * 16);
            }
        }
    }
    CP_COMMIT();
    __syncthreads();                 // publish U stores

    // ---- persistent U A-fragments (hi/lo fp16) ----
    uint32_t auh[4][4], aul[4][4];
    {
        const uint32_t abase = (16 * m + (l & 15)) * VSTR + (l >> 4) * 16;
        #pragma unroll
        for (int kk = 0; kk < 4; kk++) {
            ldsm4(auh[kk], sb + SM_UH + abase + kk * 32);
            ldsm4(aul[kk], sb + SM_UL + abase + kk * 32);
        }
    }
    __syncthreads();                 // all U reads done before any loop cp

    // ldmatrix lane bases WITHIN a quarter plane
    const uint32_t g1base = ((l & 7) + (l >> 4) * 8) * VSTR + ((l >> 3) & 1) * 16;
    const uint32_t g2base = ((l & 7) + ((l >> 3) & 1) * 8) * VSTR + (l >> 4) * 16;

    float num[8][4] = {};
    float den0 = 0.f, den1 = 0.f;
    float m0 = 0.f, m1 = 0.f;        // running row maxes, LOG2 domain

    const int r0 = 16 * m + (l >> 2), r1 = r0 + 8;
    const int cb = 2 * (l & 3);
    const long adjr0 = (long)(u0 + r0) * I_DIM + 32 * q + cb + (long)tg0 * BN;
    const long adjr1 = adjr0 + 8L * I_DIM;
    const int barid = 1 + q;

    int bcur = 0;                    // buffer index t % 3

    #pragma unroll 1
    for (int t = 0; t < NTC; t++) {
        const int bnext = (bcur == 2) ? 0 : bcur + 1;

        // stage this quarter's slice of tile t+1 into buf bnext (own half)
        if (t + 1 < NTC) {
            const long src = (((long)(tg0 + t + 1)) * 128 + 32 * q) * VSTR + half;
            const uint32_t dh = sb + qbase + bnext * QBUF + half;
            const uint32_t dl = dh + QPLANE;
            #pragma unroll
            for (int k = 0; k < 5; k++) {
                const int idx = l + 32 * k;
                if (idx < 144) {
                    cp16(dh + idx * 16, vhib + src + idx * 16);
                    cp16(dl + idx * 16, vlob + src + idx * 16);
                }
            }
        }
        CP_COMMIT();

        // adj for this tile (overlaps the wait)
        int2 a0r[4], a1r[4];
        {
            const int2* p0 = (const int2*)(adj + adjr0 + (long)t * BN);
            const int2* p1 = (const int2*)(adj + adjr1 + (long)t * BN);
            #pragma unroll
            for (int nt = 0; nt < 4; nt++) { a0r[nt] = p0[4 * nt]; a1r[nt] = p1[4 * nt]; }
        }

        CP_WAIT1();                  // own tile-t slice complete
        PAIR_BAR(barid);             // partner's slice complete + published

        const uint32_t vhi = sb + qbase + bcur * QBUF;
        const uint32_t vlo = vhi + QPLANE;

        // ---- GEMM1(t): S'[16 x 32] = U' x V^T, round-robin accumulators ----
        float s[4][4] = {};
        #pragma unroll
        for (int kk = 0; kk < 4; kk++) {
            const uint32_t off0 = kk * 32;
            const uint32_t off1 = 16 * VSTR + kk * 32;
            uint32_t b0h[4], b1h[4], b0l[4], b1l[4];
            ldsm4(b0h, vhi + g1base + off0);
            ldsm4(b1h, vhi + g1base + off1);
            ldsm4(b0l, vlo + g1base + off0);
            ldsm4(b1l, vlo + g1base + off1);
            mma16816(s[0], auh[kk], b0h[0], b0h[1]);
            mma16816(s[1], auh[kk], b0h[2], b0h[3]);
            mma16816(s[2], auh[kk], b1h[0], b1h[1]);
            mma16816(s[3], auh[kk], b1h[2], b1h[3]);
            mma16816(s[0], auh[kk], b0l[0], b0l[1]);
            mma16816(s[1], auh[kk], b0l[2], b0l[3]);
            mma16816(s[2], auh[kk], b1l[0], b1l[1]);
            mma16816(s[3], auh[kk], b1l[2], b1l[3]);
            mma16816(s[0], aul[kk], b0h[0], b0h[1]);
            mma16816(s[1], aul[kk], b0h[2], b0h[3]);
            mma16816(s[2], aul[kk], b1h[0], b1h[1]);
            mma16816(s[3], aul[kk], b1h[2], b1h[3]);
        }

        // ---- epilogue(t), log2 domain, MUFU overlapped with SHFL ----
        float mt0 = 0.f, mt1 = 0.f;
        #pragma unroll
        for (int nt = 0; nt < 4; nt++) {
            s[nt][0] = (a0r[nt].x > 0) ? s[nt][0] : 0.f;
            s[nt][1] = (a0r[nt].y > 0) ? s[nt][1] : 0.f;
            s[nt][2] = (a1r[nt].x > 0) ? s[nt][2] : 0.f;
            s[nt][3] = (a1r[nt].y > 0) ? s[nt][3] : 0.f;
            mt0 = fmaxf(mt0, fmaxf(s[nt][0], s[nt][1]));
            mt1 = fmaxf(mt1, fmaxf(s[nt][2], s[nt][3]));
        }
        // p_raw = exp2(s - m_old): issue NOW so MUFU overlaps the shfl tree
        float pr[4][4];
        float sum0 = 0.f, sum1 = 0.f;
        #pragma unroll
        for (int nt = 0; nt < 4; nt++) {
            pr[nt][0] = ex2(s[nt][0] - m0);
            pr[nt][1] = ex2(s[nt][1] - m0);
            pr[nt][2] = ex2(s[nt][2] - m1);
            pr[nt][3] = ex2(s[nt][3] - m1);
            sum0 += pr[nt][0] + pr[nt][1];
            sum1 += pr[nt][2] + pr[nt][3];
        }
        mt0 = fmaxf(mt0, __shfl_xor_sync(0xffffffffu, mt0, 1));
        mt0 = fmaxf(mt0, __shfl_xor_sync(0xffffffffu, mt0, 2));
        mt1 = fmaxf(mt1, __shfl_xor_sync(0xffffffffu, mt1, 1));
        mt1 = fmaxf(mt1, __shfl_xor_sync(0xffffffffu, mt1, 2));

        const float m0n = fmaxf(m0, mt0), m1n = fmaxf(m1, mt1);
        const float sc0 = ex2(m0 - m0n), sc1 = ex2(m1 - m1n);
        den0 = (den0 + sum0) * sc0;
        den1 = (den1 + sum1) * sc1;
        #pragma unroll
        for (int nd = 0; nd < 8; nd++) {
            num[nd][0] *= sc0; num[nd][1] *= sc0;
            num[nd][2] *= sc1; num[nd][3] *= sc1;
        }
        m0 = m0n; m1 = m1n;

        uint32_t pA[4], pB[4];
        #pragma unroll
        for (int nt = 0; nt < 4; nt++) {
            pA[nt] = packh2(pr[nt][0] * sc0, pr[nt][1] * sc0);
            pB[nt] = packh2(pr[nt][2] * sc1, pr[nt][3] * sc1);
        }

        // ---- GEMM2(t): num += P'(t) x V(t) (hi plane) ----
        #pragma unroll
        for (int kk = 0; kk < 2; kk++) {
            const uint32_t ah0 = pA[2 * kk], ah1 = pB[2 * kk], ah2 = pA[2 * kk + 1], ah3 = pB[2 * kk + 1];
            #pragma unroll
            for (int jd = 0; jd < 4; jd++) {
                const uint32_t off = kk * (16 * VSTR) + jd * 32;
                uint32_t bh0, bh1, bh2, bh3;
                ldsm4t(bh0, bh1, bh2, bh3, vhi + g2base + off);
                mma16816v(num[2 * jd],     ah0, ah1, ah2, ah3, bh0, bh1);
                mma16816v(num[2 * jd + 1], ah0, ah1, ah2, ah3, bh2, bh3);
            }
        }
        bcur = bnext;
    }
    __syncthreads();        // all V reads complete before aliasing smem

    // ---- end phase: merge (m, den, num) across item quarters; write partials ----
    float* dens = (float*)(smc + SM_DEN);          // [4][32]
    float* ms   = (float*)(smc + SM_DEN + 512);    // [4][32]
    float* numq = (float*)(smc + SM_NUMA);         // [4][32][68] fp32 (aliases V)

    if ((l & 3) == 0) { ms[q * 32 + r0] = m0; ms[q * 32 + r1] = m1; }
    __syncthreads();
    const float M0 = fmaxf(fmaxf(ms[r0], ms[32 + r0]), fmaxf(ms[64 + r0], ms[96 + r0]));
    const float M1 = fmaxf(fmaxf(ms[r1], ms[32 + r1]), fmaxf(ms[64 + r1], ms[96 + r1]));
    const float f0 = ex2(m0 - M0), f1 = ex2(m1 - M1);

    #pragma unroll
    for (int nd = 0; nd < 8; nd++) {
        *(float2*)(numq + q * (32 * 68) + r0 * 68 + 8 * nd + cb) =
            make_float2(num[nd][0] * f0, num[nd][1] * f0);
        *(float2*)(numq + q * (32 * 68) + r1 * 68 + 8 * nd + cb) =
            make_float2(num[nd][2] * f1, num[nd][3] * f1);
    }
    den0 += __shfl_xor_sync(0xffffffffu, den0, 1);
    den0 += __shfl_xor_sync(0xffffffffu, den0, 2);
    den1 += __shfl_xor_sync(0xffffffffu, den1, 1);
    den1 += __shfl_xor_sync(0xffffffffu, den1, 2);
    if ((l & 3) == 0) { dens[q * 32 + r0] = den0 * f0; dens[q * 32 + r1] = den1 * f1; }
    __syncthreads();

    // reduce num across q and write partial numerator to gmem
    {
        const int row = tid >> 3, c0 = (tid & 7) * 8;
        float acc[8];
        #pragma unroll
        for (int j = 0; j < 8; j++) acc[j] = numq[row * 68 + c0 + j];
        #pragma unroll
        for (int qq = 1; qq < 4; qq++)
            #pragma unroll
            for (int j = 0; j < 8; j++)
                acc[j] += numq[qq * (32 * 68) + row * 68 + c0 + j];
        *(float4*)&g_pnum[bid][row][c0]     = make_float4(acc[0], acc[1], acc[2], acc[3]);
        *(float4*)&g_pnum[bid][row][c0 + 4] = make_float4(acc[4], acc[5], acc[6], acc[7]);
    }
    if (tid < 32) {
        g_pden[bid][tid] = dens[tid] + dens[32 + tid] + dens[64 + tid] + dens[96 + tid];
        g_pm[bid][tid]   = fmaxf(fmaxf(ms[tid], ms[32 + tid]), fmaxf(ms[64 + tid], ms[96 + tid]));
    }
}

// ---- merge the NCH item-chunk partials per u-block, normalize, apply W ----
__global__ void __launch_bounds__(256)
merge_kernel(const float* __restrict__ Wmat, float* __restrict__ out)
{
    __shared__ float Ws[4096];
    __shared__ float amg[BM * 68];
    __shared__ float dinvs[BM];
    const int tid = threadIdx.x;
    const int ub  = blockIdx.x;
    const int base = ub * 4;

    #pragma unroll
    for (int j = 0; j < 16; j++) Ws[tid + 256 * j] = Wmat[tid + 256 * j];

    const int row = tid >> 3, c0 = (tid & 7) * 8;

    const float mm0 = g_pm[base + 0][row], mm1 = g_pm[base + 1][row];
    const float mm2 = g_pm[base + 2][row], mm3 = g_pm[base + 3][row];
    const float Mg  = fmaxf(fmaxf(mm0, mm1), fmaxf(mm2, mm3));
    const float w0 = ex2(mm0 - Mg), w1 = ex2(mm1 - Mg);
    const float w2 = ex2(mm2 - Mg), w3 = ex2(mm3 - Mg);

    if ((tid & 7) == 0) {
        const float den = w0 * g_pden[base + 0][row] + w1 * g_pden[base + 1][row]
                        + w2 * g_pden[base + 2][row] + w3 * g_pden[base + 3][row];
        dinvs[row] = 1.0f / den;
    }

    float acc[8];
    {
        const float4* n0 = (const float4*)&g_pnum[base + 0][row][c0];
        const float4* n1 = (const float4*)&g_pnum[base + 1][row][c0];
        const float4* n2 = (const float4*)&g_pnum[base + 2][row][c0];
        const float4* n3 = (const float4*)&g_pnum[base + 3][row][c0];
        #pragma unroll
        for (int h = 0; h < 2; h++) {
            float4 a0 = n0[h], a1 = n1[h], a2 = n2[h], a3 = n3[h];
            acc[4*h + 0] = w0 * a0.x + w1 * a1.x + w2 * a2.x + w3 * a3.x;
            acc[4*h + 1] = w0 * a0.y + w1 * a1.y + w2 * a2.y + w3 * a3.y;
            acc[4*h + 2] = w0 * a0.z + w1 * a1.z + w2 * a2.z + w3 * a3.z;
            acc[4*h + 3] = w0 * a0.w + w1 * a1.w + w2 * a2.w + w3 * a3.w;
        }
    }
    #pragma unroll
    for (int j = 0; j < 8; j++) amg[row * 68 + c0 + j] = acc[j];
    __syncthreads();

    const float dinv = dinvs[row];
    float o[8] = {};
    #pragma unroll 8
    for (int k = 0; k < 64; k++) {
        const float a = amg[row * 68 + k];
        const float4 wv0 = *(const float4*)(Ws + k * 64 + c0);
        const float4 wv1 = *(const float4*)(Ws + k * 64 + c0 + 4);
        o[0] = fmaf(a, wv0.x, o[0]); o[1] = fmaf(a, wv0.y, o[1]);
        o[2] = fmaf(a, wv0.z, o[2]); o[3] = fmaf(a, wv0.w, o[3]);
        o[4] = fmaf(a, wv1.x, o[4]); o[5] = fmaf(a, wv1.y, o[5]);
        o[6] = fmaf(a, wv1.z, o[6]); o[7] = fmaf(a, wv1.w, o[7]);
    }
    float4* op = (float4*)(out + (long)(ub * BM + row) * OUT_DIM + c0);
    op[0] = make_float4(o[0] * dinv, o[1] * dinv, o[2] * dinv, o[3] * dinv);
    op[1] = make_float4(o[4] * dinv, o[5] * dinv, o[6] * dinv, o[7] * dinv);
}

extern "C" void kernel_launch(void* const* d_in, const int* in_sizes, int n_in,
                              void* d_out, int out_size)
{
    const float* user_emb = (const float*)d_in[0];
    const float* item_emb = (const float*)d_in[1];
    const float* Wmat     = (const float*)d_in[2];
    const int*   adj      = (const int*)d_in[3];
    float*       out      = (float*)d_out;

    vsplit_kernel<<<I_DIM * D_DIM / 8 / 256, 256>>>(item_emb);
    cudaFuncSetAttribute(atten_hmma_kernel,
                         cudaFuncAttributeMaxDynamicSharedMemorySize, SMEM_TOTAL);
    atten_hmma_kernel<<<(U_DIM / BM) * NCH, 256, SMEM_TOTAL>>>(user_emb, adj);
    merge_kernel<<<U_DIM / BM, 256>>>(Wmat, out);
}

// round 17
// speedup vs baseline: 1.0501x; 1.0501x over previous
#include <cuda_runtime.h>
#include <cuda_fp16.h>
#include <cstdint>

// AttenConv round 16: per-quarter pipelines + item k-PERMUTATION for
// coalesced adj loads + log2-domain exp (r14 epilogue order).
// out[u,:] = softmax_i(adj?<U_u,V_i>:0) @ V @ W
// Items within each 32-group are stored at smem row perm(j)=2(j>>3)+(j&1)+8((j&7)>>1),
// so each lane's 16 mask values are CONTIGUOUS (two int4 per row; 4x LDG.128
// replaces 8x scattered LDG.64 -> ~-15% L1 wavefronts). GEMM math is
// permutation-invariant; mask<->fragment mapping adjusted accordingly.

#define U_DIM   8192
#define I_DIM   16384
#define D_DIM   64
#define OUT_DIM 64
#define BM      32          // users per CTA
#define BN      128         // items per tile
#define NCH     4           // item chunks (CTAs per u-block)
#define NTC     32          // tiles per CTA
#define VSTR    144         // bytes per 64-half row
#define QPLANE  4608        // one quarter plane: 32 rows * 144B
#define QBUF    9216        // hi+lo planes of one quarter buf
#define QSTRIDE 27648       // 3 bufs per quarter
#define LOG2E   1.44269504088896f

// smem layout: [quarter q][buf 0..2][hi|lo] then den/ms
#define SM_DEN  110592               // dens[4][32] 512 + ms[4][32] 512
#define SM_UH   9216                 // U hi [32][72] = quarter0 buf1 hi
#define SM_UL   13824                // U lo [32][72] = quarter0 buf1 lo
#define SM_NUMA 0                    // end-phase alias: num [4][32][68] fp32
#define SMEM_TOTAL 111616

__device__ __align__(16) __half g_vhi[I_DIM][72];
__device__ __align__(16) __half g_vlo[I_DIM][72];
__device__ __align__(16) float  g_pnum[1024][BM][D_DIM];
__device__ float g_pden[1024][BM];
__device__ float g_pm[1024][BM];      // log2-domain maxes

__device__ __forceinline__ uint32_t smem_u32(const void* p) {
    uint32_t a;
    asm("{ .reg .u64 t; cvta.to.shared.u64 t, %1; cvt.u32.u64 %0, t; }" : "=r"(a) : "l"(p));
    return a;
}
__device__ __forceinline__ void cp16(uint32_t dst, const void* src) {
    asm volatile("cp.async.cg.shared.global [%0], [%1], 16;" :: "r"(dst), "l"(src));
}
#define CP_COMMIT() asm volatile("cp.async.commit_group;" ::: "memory")
#define CP_WAIT1()  asm volatile("cp.async.wait_group 1;" ::: "memory")
#define PAIR_BAR(id) asm volatile("bar.sync %0, 64;" :: "r"(id) : "memory")

__device__ __forceinline__ float ex2(float x) {
    float y;
    asm("ex2.approx.f32 %0, %1;" : "=f"(y) : "f"(x));
    return y;
}

// NON-volatile: pure register op, lets ptxas schedule MMAs freely.
__device__ __forceinline__ void mma16816(float* d,
                                         const uint32_t* a,
                                         uint32_t b0, uint32_t b1) {
    asm("mma.sync.aligned.m16n8k16.row.col.f32.f16.f16.f32 "
        "{%0,%1,%2,%3},{%4,%5,%6,%7},{%8,%9},{%0,%1,%2,%3};"
        : "+f"(d[0]), "+f"(d[1]), "+f"(d[2]), "+f"(d[3])
        : "r"(a[0]), "r"(a[1]), "r"(a[2]), "r"(a[3]), "r"(b0), "r"(b1));
}
__device__ __forceinline__ void mma16816v(float* d,
                                          uint32_t a0, uint32_t a1, uint32_t a2, uint32_t a3,
                                          uint32_t b0, uint32_t b1) {
    asm("mma.sync.aligned.m16n8k16.row.col.f32.f16.f16.f32 "
        "{%0,%1,%2,%3},{%4,%5,%6,%7},{%8,%9},{%0,%1,%2,%3};"
        : "+f"(d[0]), "+f"(d[1]), "+f"(d[2]), "+f"(d[3])
        : "r"(a0), "r"(a1), "r"(a2), "r"(a3), "r"(b0), "r"(b1));
}
__device__ __forceinline__ void ldsm4(uint32_t* r, uint32_t addr) {
    asm volatile("ldmatrix.sync.aligned.m8n8.x4.shared.b16 {%0,%1,%2,%3}, [%4];"
                 : "=r"(r[0]), "=r"(r[1]), "=r"(r[2]), "=r"(r[3]) : "r"(addr));
}
__device__ __forceinline__ void ldsm4t(uint32_t& r0, uint32_t& r1, uint32_t& r2, uint32_t& r3,
                                       uint32_t addr) {
    asm volatile("ldmatrix.sync.aligned.m8n8.x4.trans.shared.b16 {%0,%1,%2,%3}, [%4];"
                 : "=r"(r0), "=r"(r1), "=r"(r2), "=r"(r3) : "r"(addr));
}
__device__ __forceinline__ uint32_t packh2(float x0, float x1) {
    uint32_t r;
    asm("cvt.rn.f16x2.f32 %0, %1, %2;" : "=r"(r) : "f"(x1), "f"(x0));
    return r;
}
__device__ __forceinline__ void split2h(float x0, float x1, uint32_t& h, uint32_t& l) {
    h = packh2(x0, x1);
    __half2 hv = *(__half2*)&h;
    float2 back = __half22float2(hv);
    l = packh2(x0 - back.x, x1 - back.y);
}

// ---- precompute: split item_emb into fp16 hi/lo planes, PERMUTED rows ----
// item j goes to row (j & ~31) | (2*(j32>>3) + (j32&1) + 8*((j32&7)>>1))
__global__ void __launch_bounds__(256)
vsplit_kernel(const float* __restrict__ item_emb)
{
    const int gid  = blockIdx.x * 256 + threadIdx.x;
    const int item = gid >> 3;
    const int d0   = (gid & 7) * 8;
    const int j32  = item & 31;
    const int row  = (item & ~31) | (2 * (j32 >> 3) + (j32 & 1) + 8 * ((j32 & 7) >> 1));
    const float4* vp = (const float4*)(item_emb + (long)item * D_DIM + d0);
    const float4 v0 = vp[0], v1 = vp[1];
    uint32_t h0, l0, h1, l1, h2, l2, h3, l3;
    split2h(v0.x, v0.y, h0, l0); split2h(v0.z, v0.w, h1, l1);
    split2h(v1.x, v1.y, h2, l2); split2h(v1.z, v1.w, h3, l3);
    *(uint4*)&g_vhi[row][d0] = make_uint4(h0, h1, h2, h3);
    *(uint4*)&g_vlo[row][d0] = make_uint4(l0, l1, l2, l3);
}

__global__ void __launch_bounds__(256, 2)
atten_hmma_kernel(const float* __restrict__ user_emb,
                  const int*   __restrict__ adj)
{
    extern __shared__ __align__(128) char smc[];
    const uint32_t sb = smem_u32(smc);
    const int tid = threadIdx.x;
    const int bid = blockIdx.x;
    const int ub  = bid >> 2;       // u-block
    const int ch  = bid & 3;        // item chunk
    const int w   = tid >> 5;
    const int l   = tid & 31;
    const int m   = w & 1;          // user group: rows 16m..16m+15
    const int q   = w >> 1;         // item quarter within tile
    const int u0  = ub * BM;
    const int tg0 = ch * NTC;       // first global tile index

    const char* vhib = (const char*)g_vhi;
    const char* vlob = (const char*)g_vlo;

    const uint32_t qbase = (uint32_t)q * QSTRIDE;        // smem quarter base
    const uint32_t half  = (uint32_t)m * 2304;

    // ---- prologue: stage U' = U*log2e hi/lo (quarter0 buf1); cp tile 0 ----
    {
        const int row = tid >> 3, d0 = (tid & 7) * 8;
        const float4* up = (const float4*)(user_emb + (long)(u0 + row) * D_DIM + d0);
        float4 v0 = up[0], v1 = up[1];
        v0.x *= LOG2E; v0.y *= LOG2E; v0.z *= LOG2E; v0.w *= LOG2E;
        v1.x *= LOG2E; v1.y *= LOG2E; v1.z *= LOG2E; v1.w *= LOG2E;
        uint32_t h0, l0h, h1, l1h, h2, l2h, h3, l3h;
        split2h(v0.x, v0.y, h0, l0h); split2h(v0.z, v0.w, h1, l1h);
        split2h(v1.x, v1.y, h2, l2h); split2h(v1.z, v1.w, h3, l3h);
        *(uint4*)(smc + SM_UH + row * VSTR + d0 * 2) = make_uint4(h0, h1, h2, h3);
        *(uint4*)(smc + SM_UL + row * VSTR + d0 * 2) = make_uint4(l0h, l1h, l2h, l3h);
    }
    {
        const long src = ((long)tg0 * 128 + 32 * q) * VSTR + half;
        const uint32_t dh = sb + qbase + half;
        const uint32_t dl = dh + QPLANE;
        #pragma unroll
        for (int k = 0; k < 5; k++) {
            const int idx = l + 32 * k;
            if (idx < 144) {
                cp16(dh + idx * 16, vhib + src + idx * 16);
                cp16(dl + idx * 16, vlob + src + idx * 16);
            }
        }
    }
    CP_COMMIT();
    __syncthreads();                 // publish U stores

    // ---- persistent U A-fragments (hi/lo fp16) ----
    uint32_t auh[4][4], aul[4][4];
    {
        const uint32_t abase = (16 * m + (l & 15)) * VSTR + (l >> 4) * 16;
        #pragma unroll
        for (int kk = 0; kk < 4; kk++) {
            ldsm4(auh[kk], sb + SM_UH + abase + kk * 32);
            ldsm4(aul[kk], sb + SM_UL + abase + kk * 32);
        }
    }
    __syncthreads();                 // all U reads done before any loop cp

    // ldmatrix lane bases WITHIN a quarter plane
    const uint32_t g1base = ((l & 7) + (l >> 4) * 8) * VSTR + ((l >> 3) & 1) * 16;
    const uint32_t g2base = ((l & 7) + ((l >> 3) & 1) * 8) * VSTR + (l >> 4) * 16;

    float num[8][4] = {};
    float den0 = 0.f, den1 = 0.f;
    float m0 = 0.f, m1 = 0.f;        // running row maxes, LOG2 domain

    const int r0 = 16 * m + (l >> 2), r1 = r0 + 8;
    const int cb = 2 * (l & 3);
    // coalesced adj: lane (c = l&3) owns items 8c..8c+7 of its rows
    const long adjr0 = (long)(u0 + r0) * I_DIM + 32 * q + 8 * (l & 3) + (long)tg0 * BN;
    const long adjr1 = adjr0 + 8L * I_DIM;
    const int barid = 1 + q;

    int bcur = 0;                    // buffer index t % 3

    #pragma unroll 1
    for (int t = 0; t < NTC; t++) {
        const int bnext = (bcur == 2) ? 0 : bcur + 1;

        // stage this quarter's slice of tile t+1 into buf bnext (own half)
        if (t + 1 < NTC) {
            const long src = (((long)(tg0 + t + 1)) * 128 + 32 * q) * VSTR + half;
            const uint32_t dh = sb + qbase + bnext * QBUF + half;
            const uint32_t dl = dh + QPLANE;
            #pragma unroll
            for (int k = 0; k < 5; k++) {
                const int idx = l + 32 * k;
                if (idx < 144) {
                    cp16(dh + idx * 16, vhib + src + idx * 16);
                    cp16(dl + idx * 16, vlob + src + idx * 16);
                }
            }
        }
        CP_COMMIT();

        // adj for this tile: 4x coalesced int4 (items 8c..8c+7, rows r0/r1)
        int4 aA, aB, bA, bB;
        {
            const int4* p0 = (const int4*)(adj + adjr0 + (long)t * BN);
            const int4* p1 = (const int4*)(adj + adjr1 + (long)t * BN);
            aA = p0[0]; aB = p0[1];
            bA = p1[0]; bB = p1[1];
        }

        CP_WAIT1();                  // own tile-t slice complete
        PAIR_BAR(barid);             // partner's slice complete + published

        const uint32_t vhi = sb + qbase + bcur * QBUF;
        const uint32_t vlo = vhi + QPLANE;

        // ---- GEMM1(t): S'[16 x 32] = U' x V^T, round-robin accumulators ----
        float s[4][4] = {};
        #pragma unroll
        for (int kk = 0; kk < 4; kk++) {
            const uint32_t off0 = kk * 32;
            const uint32_t off1 = 16 * VSTR + kk * 32;
            uint32_t b0h[4], b1h[4], b0l[4], b1l[4];
            ldsm4(b0h, vhi + g1base + off0);
            ldsm4(b1h, vhi + g1base + off1);
            ldsm4(b0l, vlo + g1base + off0);
            ldsm4(b1l, vlo + g1base + off1);
            mma16816(s[0], auh[kk], b0h[0], b0h[1]);
            mma16816(s[1], auh[kk], b0h[2], b0h[3]);
            mma16816(s[2], auh[kk], b1h[0], b1h[1]);
            mma16816(s[3], auh[kk], b1h[2], b1h[3]);
            mma16816(s[0], auh[kk], b0l[0], b0l[1]);
            mma16816(s[1], auh[kk], b0l[2], b0l[3]);
            mma16816(s[2], auh[kk], b1l[0], b1l[1]);
            mma16816(s[3], auh[kk], b1l[2], b1l[3]);
            mma16816(s[0], aul[kk], b0h[0], b0h[1]);
            mma16816(s[1], aul[kk], b0h[2], b0h[3]);
            mma16816(s[2], aul[kk], b1h[0], b1h[1]);
            mma16816(s[3], aul[kk], b1h[2], b1h[3]);
        }

        // ---- epilogue(t): mask (permuted mapping), max, rescale, P'(t) ----
        // row r0: aA = items (nt0 e0),(nt0 e1),(nt1 e0),(nt1 e1); aB = nt2, nt3
        s[0][0] = (aA.x > 0) ? s[0][0] : 0.f;
        s[0][1] = (aA.y > 0) ? s[0][1] : 0.f;
        s[1][0] = (aA.z > 0) ? s[1][0] : 0.f;
        s[1][1] = (aA.w > 0) ? s[1][1] : 0.f;
        s[2][0] = (aB.x > 0) ? s[2][0] : 0.f;
        s[2][1] = (aB.y > 0) ? s[2][1] : 0.f;
        s[3][0] = (aB.z > 0) ? s[3][0] : 0.f;
        s[3][1] = (aB.w > 0) ? s[3][1] : 0.f;
        // row r1
        s[0][2] = (bA.x > 0) ? s[0][2] : 0.f;
        s[0][3] = (bA.y > 0) ? s[0][3] : 0.f;
        s[1][2] = (bA.z > 0) ? s[1][2] : 0.f;
        s[1][3] = (bA.w > 0) ? s[1][3] : 0.f;
        s[2][2] = (bB.x > 0) ? s[2][2] : 0.f;
        s[2][3] = (bB.y > 0) ? s[2][3] : 0.f;
        s[3][2] = (bB.z > 0) ? s[3][2] : 0.f;
        s[3][3] = (bB.w > 0) ? s[3][3] : 0.f;

        float mt0 = 0.f, mt1 = 0.f;
        #pragma unroll
        for (int nt = 0; nt < 4; nt++) {
            mt0 = fmaxf(mt0, fmaxf(s[nt][0], s[nt][1]));
            mt1 = fmaxf(mt1, fmaxf(s[nt][2], s[nt][3]));
        }
        mt0 = fmaxf(mt0, __shfl_xor_sync(0xffffffffu, mt0, 1));
        mt0 = fmaxf(mt0, __shfl_xor_sync(0xffffffffu, mt0, 2));
        mt1 = fmaxf(mt1, __shfl_xor_sync(0xffffffffu, mt1, 1));
        mt1 = fmaxf(mt1, __shfl_xor_sync(0xffffffffu, mt1, 2));

        const float m0n = fmaxf(m0, mt0), m1n = fmaxf(m1, mt1);
        const float sc0 = ex2(m0 - m0n), sc1 = ex2(m1 - m1n);
        den0 *= sc0; den1 *= sc1;
        #pragma unroll
        for (int nd = 0; nd < 8; nd++) {
            num[nd][0] *= sc0; num[nd][1] *= sc0;
            num[nd][2] *= sc1; num[nd][3] *= sc1;
        }
        m0 = m0n; m1 = m1n;

        uint32_t pA[4], pB[4];
        #pragma unroll
        for (int nt = 0; nt < 4; nt++) {
            float p00 = ex2(s[nt][0] - m0), p01 = ex2(s[nt][1] - m0);
            float p10 = ex2(s[nt][2] - m1), p11 = ex2(s[nt][3] - m1);
            den0 += p00 + p01;
            den1 += p10 + p11;
            pA[nt] = packh2(p00, p01);
            pB[nt] = packh2(p10, p11);
        }

        // ---- GEMM2(t): num += P'(t) x V(t) (hi plane) ----
        #pragma unroll
        for (int kk = 0; kk < 2; kk++) {
            const uint32_t ah0 = pA[2 * kk], ah1 = pB[2 * kk], ah2 = pA[2 * kk + 1], ah3 = pB[2 * kk + 1];
            #pragma unroll
            for (int jd = 0; jd < 4; jd++) {
                const uint32_t off = kk * (16 * VSTR) + jd * 32;
                uint32_t bh0, bh1, bh2, bh3;
                ldsm4t(bh0, bh1, bh2, bh3, vhi + g2base + off);
                mma16816v(num[2 * jd],     ah0, ah1, ah2, ah3, bh0, bh1);
                mma16816v(num[2 * jd + 1], ah0, ah1, ah2, ah3, bh2, bh3);
            }
        }
        bcur = bnext;
    }
    __syncthreads();        // all V reads complete before aliasing smem

    // ---- end phase: merge (m, den, num) across item quarters; write partials ----
    float* dens = (float*)(smc + SM_DEN);          // [4][32]
    float* ms   = (float*)(smc + SM_DEN + 512);    // [4][32]
    float* numq = (float*)(smc + SM_NUMA);         // [4][32][68] fp32 (aliases V)

    if ((l & 3) == 0) { ms[q * 32 + r0] = m0; ms[q * 32 + r1] = m1; }
    __syncthreads();
    const float M0 = fmaxf(fmaxf(ms[r0], ms[32 + r0]), fmaxf(ms[64 + r0], ms[96 + r0]));
    const float M1 = fmaxf(fmaxf(ms[r1], ms[32 + r1]), fmaxf(ms[64 + r1], ms[96 + r1]));
    const float f0 = ex2(m0 - M0), f1 = ex2(m1 - M1);

    #pragma unroll
    for (int nd = 0; nd < 8; nd++) {
        *(float2*)(numq + q * (32 * 68) + r0 * 68 + 8 * nd + cb) =
            make_float2(num[nd][0] * f0, num[nd][1] * f0);
        *(float2*)(numq + q * (32 * 68) + r1 * 68 + 8 * nd + cb) =
            make_float2(num[nd][2] * f1, num[nd][3] * f1);
    }
    den0 += __shfl_xor_sync(0xffffffffu, den0, 1);
    den0 += __shfl_xor_sync(0xffffffffu, den0, 2);
    den1 += __shfl_xor_sync(0xffffffffu, den1, 1);
    den1 += __shfl_xor_sync(0xffffffffu, den1, 2);
    if ((l & 3) == 0) { dens[q * 32 + r0] = den0 * f0; dens[q * 32 + r1] = den1 * f1; }
    __syncthreads();

    // reduce num across q and write partial numerator to gmem
    {
        const int row = tid >> 3, c0 = (tid & 7) * 8;
        float acc[8];
        #pragma unroll
        for (int j = 0; j < 8; j++) acc[j] = numq[row * 68 + c0 + j];
        #pragma unroll
        for (int qq = 1; qq < 4; qq++)
            #pragma unroll
            for (int j = 0; j < 8; j++)
                acc[j] += numq[qq * (32 * 68) + row * 68 + c0 + j];
        *(float4*)&g_pnum[bid][row][c0]     = make_float4(acc[0], acc[1], acc[2], acc[3]);
        *(float4*)&g_pnum[bid][row][c0 + 4] = make_float4(acc[4], acc[5], acc[6], acc[7]);
    }
    if (tid < 32) {
        g_pden[bid][tid] = dens[tid] + dens[32 + tid] + dens[64 + tid] + dens[96 + tid];
        g_pm[bid][tid]   = fmaxf(fmaxf(ms[tid], ms[32 + tid]), fmaxf(ms[64 + tid], ms[96 + tid]));
    }
}

// ---- merge the NCH item-chunk partials per u-block, normalize, apply W ----
__global__ void __launch_bounds__(256)
merge_kernel(const float* __restrict__ Wmat, float* __restrict__ out)
{
    __shared__ float Ws[4096];
    __shared__ float amg[BM * 68];
    __shared__ float dinvs[BM];
    const int tid = threadIdx.x;
    const int ub  = blockIdx.x;
    const int base = ub * 4;

    #pragma unroll
    for (int j = 0; j < 16; j++) Ws[tid + 256 * j] = Wmat[tid + 256 * j];

    const int row = tid >> 3, c0 = (tid & 7) * 8;

    const float mm0 = g_pm[base + 0][row], mm1 = g_pm[base + 1][row];
    const float mm2 = g_pm[base + 2][row], mm3 = g_pm[base + 3][row];
    const float Mg  = fmaxf(fmaxf(mm0, mm1), fmaxf(mm2, mm3));
    const float w0 = ex2(mm0 - Mg), w1 = ex2(mm1 - Mg);
    const float w2 = ex2(mm2 - Mg), w3 = ex2(mm3 - Mg);

    if ((tid & 7) == 0) {
        const float den = w0 * g_pden[base + 0][row] + w1 * g_pden[base + 1][row]
                        + w2 * g_pden[base + 2][row] + w3 * g_pden[base + 3][row];
        dinvs[row] = 1.0f / den;
    }

    float acc[8];
    {
        const float4* n0 = (const float4*)&g_pnum[base + 0][row][c0];
        const float4* n1 = (const float4*)&g_pnum[base + 1][row][c0];
        const float4* n2 = (const float4*)&g_pnum[base + 2][row][c0];
        const float4* n3 = (const float4*)&g_pnum[base + 3][row][c0];
        #pragma unroll
        for (int h = 0; h < 2; h++) {
            float4 a0 = n0[h], a1 = n1[h], a2 = n2[h], a3 = n3[h];
            acc[4*h + 0] = w0 * a0.x + w1 * a1.x + w2 * a2.x + w3 * a3.x;
            acc[4*h + 1] = w0 * a0.y + w1 * a1.y + w2 * a2.y + w3 * a3.y;
            acc[4*h + 2] = w0 * a0.z + w1 * a1.z + w2 * a2.z + w3 * a3.z;
            acc[4*h + 3] = w0 * a0.w + w1 * a1.w + w2 * a2.w + w3 * a3.w;
        }
    }
    #pragma unroll
    for (int j = 0; j < 8; j++) amg[row * 68 + c0 + j] = acc[j];
    __syncthreads();

    const float dinv = dinvs[row];
    float o[8] = {};
    #pragma unroll 8
    for (int k = 0; k < 64; k++) {
        const float a = amg[row * 68 + k];
        const float4 wv0 = *(const float4*)(Ws + k * 64 + c0);
        const float4 wv1 = *(const float4*)(Ws + k * 64 + c0 + 4);
        o[0] = fmaf(a, wv0.x, o[0]); o[1] = fmaf(a, wv0.y, o[1]);
        o[2] = fmaf(a, wv0.z, o[2]); o[3] = fmaf(a, wv0.w, o[3]);
        o[4] = fmaf(a, wv1.x, o[4]); o[5] = fmaf(a, wv1.y, o[5]);
        o[6] = fmaf(a, wv1.z, o[6]); o[7] = fmaf(a, wv1.w, o[7]);
    }
    float4* op = (float4*)(out + (long)(ub * BM + row) * OUT_DIM + c0);
    op[0] = make_float4(o[0] * dinv, o[1] * dinv, o[2] * dinv, o[3] * dinv);
    op[1] = make_float4(o[4] * dinv, o[5] * dinv, o[6] * dinv, o[7] * dinv);
}

extern "C" void kernel_launch(void* const* d_in, const int* in_sizes, int n_in,
                              void* d_out, int out_size)
{
    const float* user_emb = (const float*)d_in[0];
    const float* item_emb = (const float*)d_in[1];
    const float* Wmat     = (const float*)d_in[2];
    const int*   adj      = (const int*)d_in[3];
    float*       out      = (float*)d_out;

    vsplit_kernel<<<I_DIM * D_DIM / 8 / 256, 256>>>(item_emb);
    cudaFuncSetAttribute(atten_hmma_kernel,
                         cudaFuncAttributeMaxDynamicSharedMemorySize, SMEM_TOTAL);
    atten_hmma_kernel<<<(U_DIM / BM) * NCH, 256, SMEM_TOTAL>>>(user_emb, adj);
    merge_kernel<<<U_DIM / BM, 256>>>(Wmat, out);
}